// round 3
// baseline (speedup 1.0000x reference)
#include <cuda_runtime.h>
#include <math.h>

// Problem constants
#define B_    4
#define H_    8
#define E_    64
#define L_    2048
#define N_    2048           // FFT length
#define LF_   1025           // rfft bins
#define BH_   32             // B*H
#define CC_   128            // 2*E (interleaved re/im)

// ---------------- device scratch (no allocations allowed) ----------------
__device__ float g_Qf[(size_t)BH_ * LF_ * CC_];   // [bh][x][2e+{0,1}]  ~16.8MB
__device__ float g_Kf[(size_t)BH_ * LF_ * CC_];
__device__ float g_Vf[(size_t)BH_ * LF_ * CC_];
__device__ float g_Of[(size_t)BH_ * LF_ * CC_];
__device__ float g_P [(size_t)BH_ * LF_ * LF_];   // scores -> probs, ~134.5MB
__device__ float g_twr[1024];
__device__ float g_twi[1024];

// 1/sqrt(2048)
#define ORTHO_SCALE 0.02209708691207961f

// ---------------- twiddle init ----------------
__global__ void init_tw_kernel() {
    int k = blockIdx.x * blockDim.x + threadIdx.x;
    if (k < 1024) {
        float s, c;
        // W_N^k = exp(-2*pi*i*k/2048) = exp(-i*pi*k/1024)
        sincospif(-(float)k / 1024.0f, &s, &c);
        g_twr[k] = c;
        g_twi[k] = s;
    }
}

// ---------------- shared-memory radix-2 DIT core (N=2048, 256 threads) ----
__device__ __forceinline__ void fft_core(float* sr, float* si, bool inverse) {
    #pragma unroll 1
    for (int s = 1; s <= 11; s++) {
        int half  = 1 << (s - 1);
        int shift = 11 - s;
        for (int j = threadIdx.x; j < 1024; j += 256) {
            int pos = j & (half - 1);
            int i1  = ((j >> (s - 1)) << s) + pos;
            int i2  = i1 + half;
            int ti  = pos << shift;
            float wr = g_twr[ti];
            float wi = inverse ? -g_twi[ti] : g_twi[ti];
            float xr = sr[i2], xi = si[i2];
            float tr = wr * xr - wi * xi;
            float tq = wr * xi + wi * xr;
            float ar = sr[i1], ai = si[i1];
            sr[i2] = ar - tr;  si[i2] = ai - tq;
            sr[i1] = ar + tr;  si[i1] = ai + tq;
        }
        __syncthreads();
    }
}

// ---------------- forward rfft for q/k/v ----------------
// grid (B*H*E, 3), block 256
__global__ void fft_fwd_kernel(const float* __restrict__ q,
                               const float* __restrict__ k,
                               const float* __restrict__ v) {
    __shared__ float sr[2048];
    __shared__ float si[2048];
    int bhe = blockIdx.x;
    int t   = blockIdx.y;
    int b = bhe >> 9;              // /(H*E)=512
    int h = (bhe >> 6) & 7;
    int e = bhe & 63;
    const float* src = (t == 0) ? q : ((t == 1) ? k : v);
    const float* base = src + (size_t)b * L_ * (H_ * E_) + h * E_ + e;

    for (int l = threadIdx.x; l < 2048; l += 256) {
        int r = __brev((unsigned)l) >> 21;   // 11-bit bit reversal
        sr[r] = base[(size_t)l * (H_ * E_)];
        si[r] = 0.0f;
    }
    __syncthreads();
    fft_core(sr, si, false);

    float* dst = (t == 0) ? g_Qf : ((t == 1) ? g_Kf : g_Vf);
    int bh = b * H_ + h;
    float* o = dst + (size_t)bh * LF_ * CC_;
    for (int x = threadIdx.x; x < LF_; x += 256) {
        o[(size_t)x * CC_ + 2 * e]     = sr[x] * ORTHO_SCALE;
        o[(size_t)x * CC_ + 2 * e + 1] = si[x] * ORTHO_SCALE;
    }
}

// ---------------- scores: |Q^H conj(K)|/sqrt(E) ----------------
// tile 64x64, 256 threads (16x16), 4x4 micro-tile, dynamic smem 2*64*130 floats
#define SC_PAD 130
#define SCORES_SMEM (2 * 64 * SC_PAD * 4)

__global__ void scores_kernel() {
    extern __shared__ float sh[];
    float* Qs = sh;                  // [64][130]
    float* Ks = sh + 64 * SC_PAD;    // [64][130]

    int tid = threadIdx.x;
    int tx = tid & 15;
    int ty = tid >> 4;
    int bh = blockIdx.z;
    int x0 = blockIdx.x * 64;
    int y0 = blockIdx.y * 64;

    const float* Qg = g_Qf + (size_t)bh * LF_ * CC_;
    const float* Kg = g_Kf + (size_t)bh * LF_ * CC_;

    // load tiles (float4 global -> scalar smem, zero-pad edge rows)
    for (int idx = tid; idx < 64 * 32; idx += 256) {
        int r  = idx >> 5;
        int c4 = idx & 31;
        float4 vq = make_float4(0.f, 0.f, 0.f, 0.f);
        float4 vk = make_float4(0.f, 0.f, 0.f, 0.f);
        int xq = x0 + r, yk = y0 + r;
        if (xq < LF_) vq = *(const float4*)(Qg + (size_t)xq * CC_ + c4 * 4);
        if (yk < LF_) vk = *(const float4*)(Kg + (size_t)yk * CC_ + c4 * 4);
        float* dq = Qs + r * SC_PAD + c4 * 4;
        float* dk = Ks + r * SC_PAD + c4 * 4;
        dq[0] = vq.x; dq[1] = vq.y; dq[2] = vq.z; dq[3] = vq.w;
        dk[0] = vk.x; dk[1] = vk.y; dk[2] = vk.z; dk[3] = vk.w;
    }
    __syncthreads();

    float accr[4][4];
    float acci[4][4];
    #pragma unroll
    for (int i = 0; i < 4; i++)
        #pragma unroll
        for (int j = 0; j < 4; j++) { accr[i][j] = 0.f; acci[i][j] = 0.f; }

    #pragma unroll 4
    for (int e = 0; e < 64; e++) {
        float2 qv[4], kv[4];
        #pragma unroll
        for (int i = 0; i < 4; i++)
            qv[i] = *(const float2*)&Qs[(ty + 16 * i) * SC_PAD + 2 * e];
        #pragma unroll
        for (int j = 0; j < 4; j++)
            kv[j] = *(const float2*)&Ks[(tx + 16 * j) * SC_PAD + 2 * e];
        #pragma unroll
        for (int i = 0; i < 4; i++)
            #pragma unroll
            for (int j = 0; j < 4; j++) {
                accr[i][j] += qv[i].x * kv[j].x + qv[i].y * kv[j].y;
                acci[i][j] += qv[i].y * kv[j].x - qv[i].x * kv[j].y;
            }
    }

    float* Pg = g_P + (size_t)bh * LF_ * LF_;
    #pragma unroll
    for (int i = 0; i < 4; i++) {
        int x = x0 + ty + 16 * i;
        if (x >= LF_) continue;
        #pragma unroll
        for (int j = 0; j < 4; j++) {
            int y = y0 + tx + 16 * j;
            if (y >= LF_) continue;
            float re = accr[i][j], im = acci[i][j];
            // /sqrt(E)=0.125, /T (T=1)
            Pg[(size_t)x * LF_ + y] = sqrtf(re * re + im * im) * 0.125f;
        }
    }
}

// ---------------- row softmax over y (1025) ----------------
// grid (1025, 32), 256 threads
__global__ void softmax_kernel() {
    __shared__ float buf[LF_];
    __shared__ float red[256];
    int tid = threadIdx.x;
    int x  = blockIdx.x;
    int bh = blockIdx.y;
    float* row = g_P + ((size_t)bh * LF_ + x) * LF_;

    float m = -3.4e38f;
    for (int i = tid; i < LF_; i += 256) {
        float val = row[i];
        buf[i] = val;
        m = fmaxf(m, val);
    }
    red[tid] = m;
    __syncthreads();
    for (int s = 128; s > 0; s >>= 1) {
        if (tid < s) red[tid] = fmaxf(red[tid], red[tid + s]);
        __syncthreads();
    }
    float mx = red[0];
    __syncthreads();

    float sum = 0.f;
    for (int i = tid; i < LF_; i += 256) {
        float e = __expf(buf[i] - mx);
        buf[i] = e;
        sum += e;
    }
    red[tid] = sum;
    __syncthreads();
    for (int s = 128; s > 0; s >>= 1) {
        if (tid < s) red[tid] += red[tid + s];
        __syncthreads();
    }
    float inv = 1.0f / red[0];
    for (int i = tid; i < LF_; i += 256)
        row[i] = buf[i] * inv;
}

// ---------------- output mix: Of[x][c] = sum_y P[x][y] * Vf[y][c] ----------
// grid (ceil(1025/32)=33, 32), 256 threads
#define OG_PPAD 66
#define OG_VPAD 130
__global__ void outgemm_kernel() {
    __shared__ float Ps[32 * OG_PPAD];   // [32 x-rows][64 y + pad]
    __shared__ float Vs[64 * OG_VPAD];   // [64 y-rows][128 c + pad]

    int tid = threadIdx.x;
    int c2 = tid & 63;     // float2 column 0..63 (covers 128 floats)
    int rg = tid >> 6;     // 0..3 -> rows rg*8..rg*8+7
    int bh = blockIdx.y;
    int x0 = blockIdx.x * 32;

    const float* Pg = g_P + (size_t)bh * LF_ * LF_;
    const float* Vg = g_Vf + (size_t)bh * LF_ * CC_;

    float2 acc[8];
    #pragma unroll
    for (int r = 0; r < 8; r++) acc[r] = make_float2(0.f, 0.f);

    for (int yt = 0; yt < 17; yt++) {
        int y0 = yt * 64;
        // P tile 32x64
        for (int idx = tid; idx < 32 * 64; idx += 256) {
            int r = idx >> 6, c = idx & 63;
            int xx = x0 + r, yy = y0 + c;
            Ps[r * OG_PPAD + c] =
                (xx < LF_ && yy < LF_) ? Pg[(size_t)xx * LF_ + yy] : 0.f;
        }
        // V tile 64x128
        for (int idx = tid; idx < 64 * 32; idx += 256) {
            int r = idx >> 5, c4 = idx & 31;
            int yy = y0 + r;
            float4 v = make_float4(0.f, 0.f, 0.f, 0.f);
            if (yy < LF_) v = *(const float4*)(Vg + (size_t)yy * CC_ + c4 * 4);
            float* d = Vs + r * OG_VPAD + c4 * 4;
            d[0] = v.x; d[1] = v.y; d[2] = v.z; d[3] = v.w;
        }
        __syncthreads();

        #pragma unroll 4
        for (int y = 0; y < 64; y++) {
            float2 v = *(const float2*)&Vs[y * OG_VPAD + 2 * c2];
            #pragma unroll
            for (int r = 0; r < 8; r++) {
                float p = Ps[(rg * 8 + r) * OG_PPAD + y];
                acc[r].x += p * v.x;
                acc[r].y += p * v.y;
            }
        }
        __syncthreads();
    }

    float* Og = g_Of + (size_t)bh * LF_ * CC_;
    #pragma unroll
    for (int r = 0; r < 8; r++) {
        int x = x0 + rg * 8 + r;
        if (x < LF_)
            *(float2*)(Og + (size_t)x * CC_ + 2 * c2) = acc[r];
    }
}

// ---------------- inverse: Hermitian extend + inverse FFT, real part -------
// grid (B*H*E), 256 threads
__global__ void fft_inv_kernel(float* __restrict__ out) {
    __shared__ float sr[2048];
    __shared__ float si[2048];
    __shared__ float xr[LF_];
    __shared__ float xi[LF_];

    int bhe = blockIdx.x;
    int b = bhe >> 9;
    int h = (bhe >> 6) & 7;
    int e = bhe & 63;
    int bh = b * H_ + h;

    const float* src = g_Of + (size_t)bh * LF_ * CC_ + 2 * e;
    for (int x = threadIdx.x; x < LF_; x += 256) {
        xr[x] = src[(size_t)x * CC_];
        xi[x] = src[(size_t)x * CC_ + 1];
    }
    __syncthreads();

    for (int k = threadIdx.x; k < 2048; k += 256) {
        float vr, vi;
        if (k <= 1024) { vr = xr[k];        vi = xi[k]; }
        else           { vr = xr[2048 - k]; vi = -xi[2048 - k]; }
        int r = __brev((unsigned)k) >> 21;
        sr[r] = vr;
        si[r] = vi;
    }
    __syncthreads();
    fft_core(sr, si, true);

    float* o = out + (size_t)b * L_ * (H_ * E_) + h * E_ + e;
    for (int l = threadIdx.x; l < 2048; l += 256)
        o[(size_t)l * (H_ * E_)] = sr[l] * ORTHO_SCALE;
}

// ---------------- launch ----------------
extern "C" void kernel_launch(void* const* d_in, const int* in_sizes, int n_in,
                              void* d_out, int out_size) {
    (void)in_sizes; (void)n_in; (void)out_size;
    const float* q = (const float*)d_in[0];
    const float* k = (const float*)d_in[1];
    const float* v = (const float*)d_in[2];
    float* out = (float*)d_out;

    cudaFuncSetAttribute(scores_kernel,
                         cudaFuncAttributeMaxDynamicSharedMemorySize,
                         SCORES_SMEM);

    init_tw_kernel<<<4, 256>>>();
    fft_fwd_kernel<<<dim3(B_ * H_ * E_, 3), 256>>>(q, k, v);
    scores_kernel<<<dim3(17, 17, BH_), 256, SCORES_SMEM>>>();
    softmax_kernel<<<dim3(LF_, BH_), 256>>>();
    outgemm_kernel<<<dim3(33, BH_), 256>>>();
    fft_inv_kernel<<<B_ * H_ * E_, 256>>>(out);
}